// round 9
// baseline (speedup 1.0000x reference)
#include <cuda_runtime.h>
#include <cuda_fp16.h>

#define LUT5 59049      // 9^5
#define HW   (1024*1024)
#define NPIX (4*HW)

#define BLK     512         // 8^3 base-index blocks over dims 2,3,4
#define NENT    (81*BLK)    // stage-1 entries (9x9 grid over dims 0,1)
// Stage 1 (as before): entry = 40 fp16 (5 ch x 8 corners of dims 2,3,4), 128B stride.
__device__ __align__(128) __half g_D[NENT * 64];    // 5.3 MB

#define NCELL 32768         // 8^5 full base cells
// Stage 2: entry = all 32 corners x 5 ch = 160 fp16 in 20 uint4 slots, padded to
// 24 slots (384B = 3 lines). Slot s: j01 = s&3 (c0=(s>>1)&1, c1=s&1),
// channel c = (s<16 ? s>>2 : 4). Slot = 8 halves over t=c2*4+c3*2+c4.
__device__ __align__(128) __half g_D2[NCELL * 192]; // 12.6 MB

__global__ void pack_kernel(const float* __restrict__ lut) {
    int tid = blockIdx.x * blockDim.x + threadIdx.x;
    if (tid >= NENT * 5) return;
    int c = tid / NENT;
    int e = tid - c * NENT;
    int i01 = e >> 9;            // 0..80
    int rem = e & 511;
    int b2 = rem >> 6, b3 = (rem >> 3) & 7, b4 = rem & 7;
    int i0 = i01 / 9, i1 = i01 - (i01 / 9) * 9;
    const float* src = lut + c * LUT5 + i0 * 6561 + i1 * 729 + b2 * 81 + b3 * 9 + b4;

    __half2 h0 = __floats2half2_rn(src[0],  src[1]);    // c2=0 c3=0
    __half2 h1 = __floats2half2_rn(src[9],  src[10]);   // c2=0 c3=1
    __half2 h2 = __floats2half2_rn(src[81], src[82]);   // c2=1 c3=0
    __half2 h3 = __floats2half2_rn(src[90], src[91]);   // c2=1 c3=1

    uint4 v;
    v.x = *(unsigned*)&h0;  v.y = *(unsigned*)&h1;
    v.z = *(unsigned*)&h2;  v.w = *(unsigned*)&h3;
    *(uint4*)(g_D + (size_t)e * 64 + c * 8) = v;
}

// Copy stage-1 slots into full-cell layout. One uint4 per thread.
__global__ void pack2_kernel() {
    int tid = blockIdx.x * blockDim.x + threadIdx.x;
    if (tid >= NCELL * 20) return;
    int ent5 = tid / 20;
    int s = tid - ent5 * 20;
    int c  = s < 16 ? (s >> 2) : 4;
    int c0 = (s >> 1) & 1, c1 = s & 1;
    int i01 = ent5 >> 9;             // i0*8 + i1
    int i0 = i01 >> 3, i1 = i01 & 7;
    int b234 = ent5 & 511;
    int eOld = (((i0 + c0) * 9 + (i1 + c1)) << 9) + b234;
    ((uint4*)g_D2)[ent5 * 24 + s] = ((const uint4*)g_D)[eOld * 8 + c];
}

__device__ __forceinline__ float dot8h(uint4 q, __half2 w0, __half2 w1,
                                       __half2 w2, __half2 w3) {
    __half2 s = __hmul2(*(const __half2*)&q.x, w0);
    s = __hfma2(*(const __half2*)&q.y, w1, s);
    s = __hfma2(*(const __half2*)&q.z, w2, s);
    s = __hfma2(*(const __half2*)&q.w, w3, s);
    float2 f = __half22float2(s);
    return f.x + f.y;
}

// Warp owns 32 consecutive pixels (coalesced I/O). 8 batches of 4 pixels; each
// pixel served by an 8-lane group reading its 3-line cell entry. Owner lane
// precomputes weights once; 7 shfl broadcast, butterfly j01-reduction, 5 shfl scatter.
__global__ void __launch_bounds__(256)
lut_kernel(const float* __restrict__ x, float* __restrict__ out) {
    const unsigned FULL = 0xffffffffu;
    int lane = threadIdx.x & 31;
    int gw   = (blockIdx.x * blockDim.x + threadIdx.x) >> 5;
    int p    = gw * 32 + lane;
    int b    = p >> 20;
    int hw   = p & (HW - 1);
    size_t iobase = (size_t)b * 5 * HW + hw;

    // ---- owner lane: per-pixel parameters ----
    float xs0 = fminf(fmaxf(x[iobase + 0 * (size_t)HW] * 8.0f, 0.0f), 7.9999995f);
    float xs1 = fminf(fmaxf(x[iobase + 1 * (size_t)HW] * 8.0f, 0.0f), 7.9999995f);
    float xs2 = fminf(fmaxf(x[iobase + 2 * (size_t)HW] * 8.0f, 0.0f), 7.9999995f);
    float xs3 = fminf(fmaxf(x[iobase + 3 * (size_t)HW] * 8.0f, 0.0f), 7.9999995f);
    float xs4 = fminf(fmaxf(x[iobase + 4 * (size_t)HW] * 8.0f, 0.0f), 7.9999995f);

    float f0 = floorf(xs0), f1 = floorf(xs1), f2 = floorf(xs2),
          f3 = floorf(xs3), f4 = floorf(xs4);
    float fr0 = xs0 - f0, fr1 = xs1 - f1, fr2 = xs2 - f2,
          fr3 = xs3 - f3, fr4 = xs4 - f4;
    int ent5 = ((((((int)f0 << 3) + (int)f1) << 3) + (int)f2) << 6)
             + ((int)f3 << 3) + (int)f4;

    float w2a = 1.0f - fr2, w2b = fr2;
    float w3a = 1.0f - fr3, w3b = fr3;
    float w4a = 1.0f - fr4, w4b = fr4;
    float t0 = w2a * w3a, t1 = w2a * w3b, t2 = w2b * w3a, t3 = w2b * w3b;
    __half2 hcw0 = __floats2half2_rn(t0 * w4a, t0 * w4b);
    __half2 hcw1 = __floats2half2_rn(t1 * w4a, t1 * w4b);
    __half2 hcw2 = __floats2half2_rn(t2 * w4a, t2 * w4b);
    __half2 hcw3 = __floats2half2_rn(t3 * w4a, t3 * w4b);
    unsigned cw0 = *(unsigned*)&hcw0, cw1 = *(unsigned*)&hcw1;
    unsigned cw2 = *(unsigned*)&hcw2, cw3 = *(unsigned*)&hcw3;

    int l = lane & 7;                 // lane within 8-lane group
    int g = lane >> 3;                // group (pixel-in-batch)
    int myk   = lane >> 2;            // batch that computes this lane's pixel
    int scsrc = (lane & 3) * 8;       // scatter source base lane
    bool sel0 = (l & 2) != 0, sel1 = (l & 1) != 0;

    const uint4* Dq = (const uint4*)g_D2;
    float o0, o1, o2, o3, o4;

#pragma unroll
    for (int k = 0; k < 8; k++) {
        int q = k * 4 + g;            // pixel-in-warp served by this group
        int      eq  = __shfl_sync(FULL, ent5, q);
        float    a0  = __shfl_sync(FULL, fr0,  q);
        float    a1  = __shfl_sync(FULL, fr1,  q);
        unsigned u0  = __shfl_sync(FULL, cw0,  q);
        unsigned u1  = __shfl_sync(FULL, cw1,  q);
        unsigned u2  = __shfl_sync(FULL, cw2,  q);
        unsigned u3  = __shfl_sync(FULL, cw3,  q);
        __half2 hw0 = *(__half2*)&u0, hw1 = *(__half2*)&u1;
        __half2 hw2 = *(__half2*)&u2, hw3 = *(__half2*)&u3;

        float pw = (sel0 ? a0 : 1.0f - a0) * (sel1 ? a1 : 1.0f - a1);

        const uint4* base = Dq + eq * 24;
        uint4 qa = base[l];                 // line 0: ch {0,1}, j01 = l&3
        uint4 qb = base[8 + l];             // line 1: ch {2,3}
        uint4 qc = base[16 + (l & 3)];      // line 2 (first half): ch 4

        float pA = pw * dot8h(qa, hw0, hw1, hw2, hw3);
        float pB = pw * dot8h(qb, hw0, hw1, hw2, hw3);
        float pC = pw * dot8h(qc, hw0, hw1, hw2, hw3);

        // reduce over j01 (lane bits 0,1)
        pA += __shfl_xor_sync(FULL, pA, 1);
        pA += __shfl_xor_sync(FULL, pA, 2);
        pB += __shfl_xor_sync(FULL, pB, 1);
        pB += __shfl_xor_sync(FULL, pB, 2);
        pC += __shfl_xor_sync(FULL, pC, 1);
        pC += __shfl_xor_sync(FULL, pC, 2);

        // scatter this batch's 4 pixels x 5 channels to owner lanes
        float s0 = __shfl_sync(FULL, pA, scsrc);      // ch0 (lanes g*8+0..3)
        float s1 = __shfl_sync(FULL, pA, scsrc + 4);  // ch1
        float s2 = __shfl_sync(FULL, pB, scsrc);      // ch2
        float s3 = __shfl_sync(FULL, pB, scsrc + 4);  // ch3
        float s4 = __shfl_sync(FULL, pC, scsrc);      // ch4
        if (k == myk) { o0 = s0; o1 = s1; o2 = s2; o3 = s3; o4 = s4; }
    }

    out[iobase + 0 * (size_t)HW] = o0;
    out[iobase + 1 * (size_t)HW] = o1;
    out[iobase + 2 * (size_t)HW] = o2;
    out[iobase + 3 * (size_t)HW] = o3;
    out[iobase + 4 * (size_t)HW] = o4;
}

extern "C" void kernel_launch(void* const* d_in, const int* in_sizes, int n_in,
                              void* d_out, int out_size) {
    const float* x   = (const float*)d_in[0];
    const float* lut = (const float*)d_in[1];
    if (n_in >= 2 && in_sizes[0] == 5 * LUT5) {
        lut = (const float*)d_in[0];
        x   = (const float*)d_in[1];
    }
    float* out = (float*)d_out;

    pack_kernel<<<(NENT * 5 + 255) / 256, 256>>>(lut);
    pack2_kernel<<<(NCELL * 20 + 255) / 256, 256>>>();

    int blocks = NPIX / (32 * 8);   // 32 px/warp, 8 warps/block
    lut_kernel<<<blocks, 256>>>(x, out);
}

// round 10
// speedup vs baseline: 1.0166x; 1.0166x over previous
#include <cuda_runtime.h>
#include <cuda_fp16.h>

#define LUT5 59049      // 9^5
#define HW   (1024*1024)
#define NPIX (4*HW)

#define BLK     512         // 8^3 base-index blocks over dims 2,3,4
#define NENT    (81*BLK)    // 41472 entries (9x9 grid over dims 0,1)
// Entry: 40 fp16 (5 ch x 8 corners of dims 2,3,4), padded to 128B stride (one line).
// Half index within entry: c*8 + t, t = c2*4 + c3*2 + c4. Halves 40..63 unused (zero).
__device__ __align__(128) __half g_D[NENT * 64];   // 5.3 MB

// Thread -> (e, c) with c fastest: adjacent lanes write adjacent 16B chunks
// (~7 lines per store instr instead of 32). Scalar loads: lut + c*59049 is only
// 4B-aligned (59049 odd), so vector loads would fault for odd c.
__global__ void pack_kernel(const float* __restrict__ lut) {
    int tid = blockIdx.x * blockDim.x + threadIdx.x;
    if (tid >= NENT * 5) return;
    int e = tid / 5;
    int c = tid - e * 5;
    int i01 = e >> 9;            // 0..80
    int rem = e & 511;
    int b2 = rem >> 6, b3 = (rem >> 3) & 7, b4 = rem & 7;
    int i0 = i01 / 9, i1 = i01 - (i01 / 9) * 9;
    const float* src = lut + c * LUT5 + i0 * 6561 + i1 * 729 + b2 * 81 + b3 * 9 + b4;

    __half2 h0 = __floats2half2_rn(src[0],  src[1]);    // c2=0 c3=0
    __half2 h1 = __floats2half2_rn(src[9],  src[10]);   // c2=0 c3=1
    __half2 h2 = __floats2half2_rn(src[81], src[82]);   // c2=1 c3=0
    __half2 h3 = __floats2half2_rn(src[90], src[91]);   // c2=1 c3=1

    uint4 v;
    v.x = *(unsigned*)&h0;  v.y = *(unsigned*)&h1;
    v.z = *(unsigned*)&h2;  v.w = *(unsigned*)&h3;
    *(uint4*)(g_D + (size_t)e * 64 + c * 8) = v;   // 16B-aligned dst
}

__device__ __forceinline__ float dot8h(uint4 q, __half2 w0, __half2 w1,
                                       __half2 w2, __half2 w3) {
    __half2 s = __hmul2(*(const __half2*)&q.x, w0);
    s = __hfma2(*(const __half2*)&q.y, w1, s);
    s = __hfma2(*(const __half2*)&q.z, w2, s);
    s = __hfma2(*(const __half2*)&q.w, w3, s);
    float2 f = __half22float2(s);
    return f.x + f.y;
}

// Warp owns 32 consecutive pixels. Coalesced load of 5 channel planes (1 line each),
// 6 compute batches of 5-lane groups, shfl redistribution, coalesced stores.
__global__ void __launch_bounds__(256, 6)
lut_kernel(const float* __restrict__ x, float* __restrict__ out) {
    const unsigned FULL = 0xffffffffu;
    int lane = threadIdx.x & 31;
    int gw   = (blockIdx.x * blockDim.x + threadIdx.x) >> 5;
    int p    = gw * 32 + lane;              // this lane's owned pixel
    int b    = p >> 20;
    int hw   = p & (HW - 1);
    size_t iobase = (size_t)b * 5 * HW + hw;   // warp-aligned: hw ≡ lane (mod 32)

    // Coalesced: lane holds all 5 channels of its pixel, pre-scaled+clamped.
    float xs0 = fminf(fmaxf(x[iobase + 0 * (size_t)HW] * 8.0f, 0.0f), 7.9999995f);
    float xs1 = fminf(fmaxf(x[iobase + 1 * (size_t)HW] * 8.0f, 0.0f), 7.9999995f);
    float xs2 = fminf(fmaxf(x[iobase + 2 * (size_t)HW] * 8.0f, 0.0f), 7.9999995f);
    float xs3 = fminf(fmaxf(x[iobase + 3 * (size_t)HW] * 8.0f, 0.0f), 7.9999995f);
    float xs4 = fminf(fmaxf(x[iobase + 4 * (size_t)HW] * 8.0f, 0.0f), 7.9999995f);

    int g  = lane / 5; if (g > 5) g = 5;    // compute group 0..5
    int ch = lane - g * 5;
    int che = ch > 4 ? 4 : ch;
    int myk = lane / 6;                      // batch in which this lane's pixel is computed
    int gs  = lane - myk * 6;                // its group index in that batch

    const uint4* Dq = (const uint4*)g_D;
    float ores[5];

#pragma unroll
    for (int k = 0; k < 6; k++) {
        int q = 6 * k + g;                   // pixel-in-warp this group handles
        bool active = q < 32;                // batch 5: only groups 0,1 real
        int qs = active ? q : 31;

        float v0 = __shfl_sync(FULL, xs0, qs);
        float v1 = __shfl_sync(FULL, xs1, qs);
        float v2 = __shfl_sync(FULL, xs2, qs);
        float v3 = __shfl_sync(FULL, xs3, qs);
        float v4 = __shfl_sync(FULL, xs4, qs);

        float f0 = floorf(v0), f1 = floorf(v1), f2 = floorf(v2),
              f3 = floorf(v3), f4 = floorf(v4);
        int i0 = (int)f0, i1 = (int)f1, i2 = (int)f2, i3 = (int)f3, i4 = (int)f4;
        float fr0 = v0 - f0, fr1 = v1 - f1, fr2 = v2 - f2,
              fr3 = v3 - f3, fr4 = v4 - f4;

        int ent = ((i0 * 9 + i1) << 9) + (i2 << 6) + (i3 << 3) + i4;

        float w0a = 1.0f - fr0, w0b = fr0;
        float w1a = 1.0f - fr1, w1b = fr1;
        float w2a = 1.0f - fr2, w2b = fr2;
        float w3a = 1.0f - fr3, w3b = fr3;
        float w4a = 1.0f - fr4, w4b = fr4;

        float pw0 = w0a * w1a, pw1 = w0a * w1b, pw2 = w0b * w1a, pw3 = w0b * w1b;
        float t0 = w2a * w3a, t1 = w2a * w3b, t2 = w2b * w3a, t3 = w2b * w3b;

        __half2 cw0 = __floats2half2_rn(t0 * w4a, t0 * w4b);
        __half2 cw1 = __floats2half2_rn(t1 * w4a, t1 * w4b);
        __half2 cw2 = __floats2half2_rn(t2 * w4a, t2 * w4b);
        __half2 cw3 = __floats2half2_rn(t3 * w4a, t3 * w4b);

        float acc = 0.0f;
        if (active) {
            uint4 q0 = Dq[(ent)            * 8 + che];
            uint4 q1 = Dq[(ent + BLK)      * 8 + che];
            uint4 q2 = Dq[(ent + 9 * BLK)  * 8 + che];
            uint4 q3 = Dq[(ent + 10 * BLK) * 8 + che];
            acc = pw0 * dot8h(q0, cw0, cw1, cw2, cw3);
            acc = fmaf(pw1, dot8h(q1, cw0, cw1, cw2, cw3), acc);
            acc = fmaf(pw2, dot8h(q2, cw0, cw1, cw2, cw3), acc);
            acc = fmaf(pw3, dot8h(q3, cw0, cw1, cw2, cw3), acc);
        }

        // Scatter this batch's 6 pixels x 5 channels back to owner lanes.
        bool mine = (k == myk);
#pragma unroll
        for (int c = 0; c < 5; c++) {
            float s = __shfl_sync(FULL, acc, (gs * 5 + c) & 31);
            if (mine) ores[c] = s;
        }
    }

    // Coalesced stores: one aligned 128B line per channel plane.
    out[iobase + 0 * (size_t)HW] = ores[0];
    out[iobase + 1 * (size_t)HW] = ores[1];
    out[iobase + 2 * (size_t)HW] = ores[2];
    out[iobase + 3 * (size_t)HW] = ores[3];
    out[iobase + 4 * (size_t)HW] = ores[4];
}

extern "C" void kernel_launch(void* const* d_in, const int* in_sizes, int n_in,
                              void* d_out, int out_size) {
    const float* x   = (const float*)d_in[0];
    const float* lut = (const float*)d_in[1];
    if (n_in >= 2 && in_sizes[0] == 5 * LUT5) {
        lut = (const float*)d_in[0];
        x   = (const float*)d_in[1];
    }
    float* out = (float*)d_out;

    pack_kernel<<<(NENT * 5 + 255) / 256, 256>>>(lut);

    int blocks = NPIX / (32 * 8);   // 32 px/warp, 8 warps/block
    lut_kernel<<<blocks, 256>>>(x, out);
}

// round 11
// speedup vs baseline: 1.1027x; 1.0848x over previous
#include <cuda_runtime.h>
#include <cuda_fp16.h>

#define LUT5 59049      // 9^5
#define HW   (1024*1024)
#define NPIX (4*HW)

#define BLK     512         // 8^3 base-index blocks over dims 2,3,4
#define NENT    (81*BLK)    // 41472 entries (9x9 grid over dims 0,1)
// Entry: 40 fp16 (5 ch x 8 corners of dims 2,3,4), padded to 128B stride (one line).
// Half index within entry: c*8 + t, t = c2*4 + c3*2 + c4. Halves 40..63 unused (zero).
__device__ __align__(128) __half g_D[NENT * 64];   // 5.3 MB

// Scalar loads: lut + c*59049 is only 4B-aligned (59049 odd), vector loads would fault.
__global__ void pack_kernel(const float* __restrict__ lut) {
    int tid = blockIdx.x * blockDim.x + threadIdx.x;
    if (tid >= NENT * 5) return;
    int e = tid / 5;
    int c = tid - e * 5;
    int i01 = e >> 9;            // 0..80
    int rem = e & 511;
    int b2 = rem >> 6, b3 = (rem >> 3) & 7, b4 = rem & 7;
    int i0 = i01 / 9, i1 = i01 - (i01 / 9) * 9;
    const float* src = lut + c * LUT5 + i0 * 6561 + i1 * 729 + b2 * 81 + b3 * 9 + b4;

    __half2 h0 = __floats2half2_rn(src[0],  src[1]);    // c2=0 c3=0
    __half2 h1 = __floats2half2_rn(src[9],  src[10]);   // c2=0 c3=1
    __half2 h2 = __floats2half2_rn(src[81], src[82]);   // c2=1 c3=0
    __half2 h3 = __floats2half2_rn(src[90], src[91]);   // c2=1 c3=1

    uint4 v;
    v.x = *(unsigned*)&h0;  v.y = *(unsigned*)&h1;
    v.z = *(unsigned*)&h2;  v.w = *(unsigned*)&h3;
    *(uint4*)(g_D + (size_t)e * 64 + c * 8) = v;   // 16B-aligned dst
}

__device__ __forceinline__ float dot8h(uint4 q, __half2 w0, __half2 w1,
                                       __half2 w2, __half2 w3) {
    __half2 s = __hmul2(*(const __half2*)&q.x, w0);
    s = __hfma2(*(const __half2*)&q.y, w1, s);
    s = __hfma2(*(const __half2*)&q.z, w2, s);
    s = __hfma2(*(const __half2*)&q.w, w3, s);
    float2 f = __half22float2(s);
    return f.x + f.y;
}

// Warp owns 32 consecutive pixels. Coalesced load of 5 channel planes (1 line each),
// 6 compute batches of 5-lane groups, smem scatter, coalesced stores.
__global__ void __launch_bounds__(256)
lut_kernel(const float* __restrict__ x, float* __restrict__ out) {
    const unsigned FULL = 0xffffffffu;
    __shared__ float sout[8][160];           // per-warp: 32 px x 5 ch
    int lane = threadIdx.x & 31;
    int wrp  = (threadIdx.x >> 5) & 7;
    int gw   = (blockIdx.x * blockDim.x + threadIdx.x) >> 5;
    int p    = gw * 32 + lane;              // this lane's owned pixel
    int b    = p >> 20;
    int hw   = p & (HW - 1);
    size_t iobase = (size_t)b * 5 * HW + hw;   // warp-aligned: hw ≡ lane (mod 32)

    // Coalesced: lane holds all 5 channels of its pixel, pre-scaled+clamped.
    float xs0 = fminf(fmaxf(x[iobase + 0 * (size_t)HW] * 8.0f, 0.0f), 7.9999995f);
    float xs1 = fminf(fmaxf(x[iobase + 1 * (size_t)HW] * 8.0f, 0.0f), 7.9999995f);
    float xs2 = fminf(fmaxf(x[iobase + 2 * (size_t)HW] * 8.0f, 0.0f), 7.9999995f);
    float xs3 = fminf(fmaxf(x[iobase + 3 * (size_t)HW] * 8.0f, 0.0f), 7.9999995f);
    float xs4 = fminf(fmaxf(x[iobase + 4 * (size_t)HW] * 8.0f, 0.0f), 7.9999995f);

    int g  = lane / 5; if (g > 5) g = 5;    // compute group 0..5
    int ch = lane - g * 5;
    int che = ch > 4 ? 4 : ch;

    const uint4* Dq = (const uint4*)g_D;

#pragma unroll
    for (int k = 0; k < 6; k++) {
        int q = 6 * k + g;                   // pixel-in-warp this group handles
        bool active = (q < 32) && (ch < 5);  // batch 5: only groups 0,1; lanes 30/31 never
        int qs = q < 32 ? q : 31;

        float v0 = __shfl_sync(FULL, xs0, qs);
        float v1 = __shfl_sync(FULL, xs1, qs);
        float v2 = __shfl_sync(FULL, xs2, qs);
        float v3 = __shfl_sync(FULL, xs3, qs);
        float v4 = __shfl_sync(FULL, xs4, qs);

        float f0 = floorf(v0), f1 = floorf(v1), f2 = floorf(v2),
              f3 = floorf(v3), f4 = floorf(v4);
        int i0 = (int)f0, i1 = (int)f1, i2 = (int)f2, i3 = (int)f3, i4 = (int)f4;
        float fr0 = v0 - f0, fr1 = v1 - f1, fr2 = v2 - f2,
              fr3 = v3 - f3, fr4 = v4 - f4;

        int ent = ((i0 * 9 + i1) << 9) + (i2 << 6) + (i3 << 3) + i4;

        float w0a = 1.0f - fr0, w0b = fr0;
        float w1a = 1.0f - fr1, w1b = fr1;
        float w2a = 1.0f - fr2, w2b = fr2;
        float w3a = 1.0f - fr3, w3b = fr3;
        float w4a = 1.0f - fr4, w4b = fr4;

        float pw0 = w0a * w1a, pw1 = w0a * w1b, pw2 = w0b * w1a, pw3 = w0b * w1b;
        float t0 = w2a * w3a, t1 = w2a * w3b, t2 = w2b * w3a, t3 = w2b * w3b;

        __half2 cw0 = __floats2half2_rn(t0 * w4a, t0 * w4b);
        __half2 cw1 = __floats2half2_rn(t1 * w4a, t1 * w4b);
        __half2 cw2 = __floats2half2_rn(t2 * w4a, t2 * w4b);
        __half2 cw3 = __floats2half2_rn(t3 * w4a, t3 * w4b);

        if (active) {
            uint4 q0 = Dq[(ent)            * 8 + che];
            uint4 q1 = Dq[(ent + BLK)      * 8 + che];
            uint4 q2 = Dq[(ent + 9 * BLK)  * 8 + che];
            uint4 q3 = Dq[(ent + 10 * BLK) * 8 + che];
            float acc;
            acc = pw0 * dot8h(q0, cw0, cw1, cw2, cw3);
            acc = fmaf(pw1, dot8h(q1, cw0, cw1, cw2, cw3), acc);
            acc = fmaf(pw2, dot8h(q2, cw0, cw1, cw2, cw3), acc);
            acc = fmaf(pw3, dot8h(q3, cw0, cw1, cw2, cw3), acc);
            // addr = q*5 + ch = 30k + lane  -> consecutive, conflict-free
            sout[wrp][30 * k + lane] = acc;
        }
    }

    __syncwarp(FULL);

    // Coalesced stores: lane reads its pixel's 5 channels (stride 5 ⊥ 32 banks).
    out[iobase + 0 * (size_t)HW] = sout[wrp][lane * 5 + 0];
    out[iobase + 1 * (size_t)HW] = sout[wrp][lane * 5 + 1];
    out[iobase + 2 * (size_t)HW] = sout[wrp][lane * 5 + 2];
    out[iobase + 3 * (size_t)HW] = sout[wrp][lane * 5 + 3];
    out[iobase + 4 * (size_t)HW] = sout[wrp][lane * 5 + 4];
}

extern "C" void kernel_launch(void* const* d_in, const int* in_sizes, int n_in,
                              void* d_out, int out_size) {
    const float* x   = (const float*)d_in[0];
    const float* lut = (const float*)d_in[1];
    if (n_in >= 2 && in_sizes[0] == 5 * LUT5) {
        lut = (const float*)d_in[0];
        x   = (const float*)d_in[1];
    }
    float* out = (float*)d_out;

    pack_kernel<<<(NENT * 5 + 255) / 256, 256>>>(lut);

    int blocks = NPIX / (32 * 8);   // 32 px/warp, 8 warps/block
    lut_kernel<<<blocks, 256>>>(x, out);
}